// round 11
// baseline (speedup 1.0000x reference)
#include <cuda_runtime.h>
#include <cstdint>

__device__ double g_rot_acc[64];
__device__ double g_str_acc[64];
__device__ unsigned int g_ticket = 0;

#define TPB 128
#define PPT 8
#define TILE (TPB * PPT)          // 1024 points per tile

// smem staging: per-tile arrays (16B chunks), XOR-swizzled
#define POS_CHUNKS 514            // 1028 float2  (pos[tb-2 .. tb+1025])
#define TH_CHUNKS  259            // 1036 float   (th [tb-4 .. tb+1031])
#define BK_CHUNKS  518            // 1036 int2    (bk [tb-4 .. tb+1031])
#define RL_CHUNKS  259            // 1036 float   (rl [tb-4 .. tb+1031])
#define POS_BYTES (520 * 16)
#define TH_BYTES  (264 * 16)
#define BK_BYTES  (520 * 16)
#define RL_BYTES  (264 * 16)
#define OFF_POS 0
#define OFF_TH  (POS_BYTES)
#define OFF_BK  (POS_BYTES + TH_BYTES)
#define OFF_RL  (POS_BYTES + TH_BYTES + BK_BYTES)
#define STAGE_BYTES (POS_BYTES + TH_BYTES + BK_BYTES + RL_BYTES)   // 25088
#define NCTAS 608                 // 152 SMs * 4 CTAs

__device__ __forceinline__ uint32_t swz16(uint32_t c) { return c ^ ((c >> 3) & 7); }

__device__ __forceinline__ void cp16(uint32_t dst, const void* src) {
    asm volatile("cp.async.cg.shared.global [%0], [%1], 16;" :: "r"(dst), "l"(src));
}

// Full branch-free atan2 (cephes core), abs err ~1e-7 rad. Rare fallback.
__device__ __noinline__ float full_atan2f(float y, float x) {
    float ay = fabsf(y), ax = fabsf(x);
    float mn = fminf(ay, ax), mx = fmaxf(ay, ax);
    bool  big = mn > 0.41421356237f * mx;
    float num = big ? (mn - mx) : mn;
    float den = big ? (mn + mx) : mx;
    float z = __fdividef(num, den);
    float s = z * z;
    float p = fmaf(fmaf(fmaf(fmaf(8.05374449538e-2f, s, -1.38776856032e-1f), s,
                             1.99777106478e-1f), s, -3.33329491539e-1f),
                   s * z, z);
    float r = big ? (0.78539816339744831f + p) : p;
    if (ay > ax) r = 1.57079632679489662f - r;
    if (x < 0.0f) r = 3.14159265358979323f - r;
    return copysignf(r, y);
}

__device__ __forceinline__ float edge_atan2f(float y, float x) {
    if (__builtin_expect(fabsf(y) <= 0.41421356237f * x, 1)) {
        float z = __fdividef(y, x);
        float s = z * z;
        return fmaf(fmaf(fmaf(fmaf(8.05374449538e-2f, s, -1.38776856032e-1f), s,
                              1.99777106478e-1f), s, -3.33329491539e-1f),
                    s * z, z);
    }
    return full_atan2f(y, x);
}

// ---------- boundary tiles: per-thread direct-LDG path (R10 slow branch) ----------
__device__ __noinline__ void compute_direct(
    const float2* __restrict__ pos, const float* __restrict__ th_ss,
    const float* __restrict__ rest, const int2* __restrict__ buckle,
    float* __restrict__ out, int H, int N, int s,
    float k_stiff, float k_soft, float k_stretch,
    float& rot_e, float& str_e)
{
    if (s >= N) return;
    float Ex[11], Ey[11], TH[10], B0[10], B1[10], RL[11];
    {
        float px[12], py[12];
        #pragma unroll
        for (int j = 0; j < 12; j++) {
            int g = max(0, min(s - 2 + j, N - 1));
            float2 v = __ldg(&pos[g]);
            px[j] = v.x; py[j] = v.y;
        }
        #pragma unroll
        for (int j = 0; j < 11; j++) {
            int e = s - 2 + j;
            bool ve = (e >= 0) && (e <= H);
            Ex[j] = ve ? (px[j + 1] - px[j]) : 1.f;
            Ey[j] = ve ? (py[j + 1] - py[j]) : 0.f;
        }
    }
    #pragma unroll
    for (int i = 0; i < 10; i++) {
        int h = s - 2 + i;
        bool v = (h >= 0) && (h < H);
        TH[i] = v ? __ldg(&th_ss[h]) : 0.f;
        int2 b = v ? __ldg(&buckle[h]) : make_int2(0, 0);
        B0[i] = (float)b.x; B1[i] = (float)b.y;
    }
    #pragma unroll
    for (int j = 0; j < 11; j++) {
        int e = s - 2 + j;
        RL[j] = ((e >= 0) && (e <= H)) ? __ldg(&rest[e]) : 1.f;
    }

    float phi[11];
    #pragma unroll
    for (int m = 0; m < 11; m++) phi[m] = edge_atan2f(Ey[m], Ex[m]);

    float c[10];
    float gprev = 0.f;
    #pragma unroll
    for (int i = 0; i < 10; i++) {
        float theta = phi[i + 1] - phi[i];
        float th = TH[i];
        bool m0 = fmaf(theta, B0[i], th) > 0.f;
        bool m1 = fmaf(theta, B1[i], th) > 0.f;
        float keff = (m0 ? k_stiff : k_soft) + (m1 ? k_stiff : k_soft);
        float diff = theta - th;
        float g = keff * diff;
        bool vh = ((s - 2 + i) >= 0) && ((s - 2 + i) < H);
        g = vh ? g : 0.f;
        if (i >= 2) rot_e = fmaf(g, diff, rot_e);
        if (i >= 1) c[i] = gprev - g;
        gprev = g;
    }

    float Gx[PPT], Gy[PPT];
    #pragma unroll
    for (int j = 0; j < PPT; j++) { Gx[j] = 0.f; Gy[j] = 0.f; }
    #pragma unroll
    for (int m = 1; m <= 9; m++) {
        float ex = Ex[m], ey = Ey[m];
        float lensq = fmaf(ex, ex, ey * ey);
        float rsq = rsqrtf(lensq);
        float len = lensq * rsq;
        float dl  = len - RL[m];
        if (m >= 2) str_e = fmaf(dl, dl, str_e);
        float fsc = k_stretch * dl * rsq;
        float psc = c[m] * rsq * rsq;
        float Fx = fmaf(fsc, ex, -psc * ey);
        float Fy = fmaf(fsc, ey,  psc * ex);
        if (m <= 8) { Gx[m - 1] += Fx; Gy[m - 1] += Fy; }
        if (m >= 2) { Gx[m - 2] -= Fx; Gy[m - 2] -= Fy; }
    }
    #pragma unroll
    for (int j = 0; j < PPT; j++) {
        int p = s + j;
        if (p < N) {
            bool z = (p < 2);
            out[3 + 2 * p]     = z ? 0.f : -Gx[j];
            out[3 + 2 * p + 1] = z ? 0.f : -Gy[j];
        }
    }
}

__global__ void __launch_bounds__(TPB, 4)
chain_kernel(const float2* __restrict__ pos,
             const float*  __restrict__ th_ss,
             const float*  __restrict__ rest,
             const float*  __restrict__ p_kstiff,
             const float*  __restrict__ p_ksoft,
             const float*  __restrict__ p_kstretch,
             const int2*   __restrict__ buckle,
             float*        __restrict__ out,
             int H, unsigned totalWarps)
{
    extern __shared__ char smemraw[];
    const int N   = H + 2;
    const int T   = (N + TILE - 1) / TILE;
    const int tid = threadIdx.x;
    const int bid = blockIdx.x;
    const int G   = gridDim.x;

    const float k_stiff   = __ldg(p_kstiff);
    const float k_soft    = __ldg(p_ksoft);
    const float k_stretch = __ldg(p_kstretch);

    float rot_e = 0.f, str_e = 0.f;

    // interior tile: entire tile fast-valid AND all staged loads in-bounds
    auto interior = [&](int tile) -> bool {
        long tb = (long)tile * TILE;
        return (tb >= 16) && (tb + 1032 <= (long)H);
    };
    auto prefetch = [&](int tile, int buf) {
        long tb = (long)tile * TILE;
        const char* pb = (const char*)pos    + (tb - 2) * 8;
        const char* tb_ = (const char*)th_ss + (tb - 4) * 4;
        const char* bb = (const char*)buckle + (tb - 4) * 8;
        const char* rb = (const char*)rest   + (tb - 4) * 4;
        uint32_t sb = (uint32_t)__cvta_generic_to_shared(smemraw + buf * STAGE_BYTES);
        for (int c = tid; c < POS_CHUNKS; c += TPB)
            cp16(sb + OFF_POS + (swz16(c) << 4), pb + ((size_t)c << 4));
        for (int c = tid; c < TH_CHUNKS; c += TPB)
            cp16(sb + OFF_TH + (swz16(c) << 4), tb_ + ((size_t)c << 4));
        for (int c = tid; c < BK_CHUNKS; c += TPB)
            cp16(sb + OFF_BK + (swz16(c) << 4), bb + ((size_t)c << 4));
        for (int c = tid; c < RL_CHUNKS; c += TPB)
            cp16(sb + OFF_RL + (swz16(c) << 4), rb + ((size_t)c << 4));
    };

    // ---------------- pipeline ----------------
    if (bid < T && interior(bid)) prefetch(bid, 0);
    asm volatile("cp.async.commit_group;");

    int k = 0;
    for (int tile = bid; tile < T; tile += G, k++) {
        int nxt = tile + G;
        if (nxt < T && interior(nxt)) prefetch(nxt, (k + 1) & 1);
        asm volatile("cp.async.commit_group;");
        asm volatile("cp.async.wait_group 1;");
        __syncthreads();

        const int tb = tile * TILE;
        const int s  = tb + tid * PPT;

        if (interior(tile)) {
            const char* st = smemraw + (k & 1) * STAGE_BYTES;

            float Ex[11], Ey[11];
            {
                float px[12], py[12];
                #pragma unroll
                for (int d = 0; d < 6; d++) {
                    float4 v = *(const float4*)(st + OFF_POS + (swz16(4 * tid + d) << 4));
                    px[2 * d] = v.x; py[2 * d] = v.y;
                    px[2 * d + 1] = v.z; py[2 * d + 1] = v.w;
                }
                #pragma unroll
                for (int j = 0; j < 11; j++) {
                    Ex[j] = px[j + 1] - px[j];
                    Ey[j] = py[j + 1] - py[j];
                }
            }
            float TH[10];
            {
                float tv[12];
                #pragma unroll
                for (int d = 0; d < 3; d++) {
                    float4 v = *(const float4*)(st + OFF_TH + (swz16(2 * tid + d) << 4));
                    tv[4 * d] = v.x; tv[4 * d + 1] = v.y;
                    tv[4 * d + 2] = v.z; tv[4 * d + 3] = v.w;
                }
                #pragma unroll
                for (int i = 0; i < 10; i++) TH[i] = tv[i + 2];
            }
            float B0[10], B1[10];
            {
                #pragma unroll
                for (int d = 1; d <= 5; d++) {
                    int4 v = *(const int4*)(st + OFF_BK + (swz16(4 * tid + d) << 4));
                    B0[2 * (d - 1)]     = (float)v.x; B1[2 * (d - 1)]     = (float)v.y;
                    B0[2 * (d - 1) + 1] = (float)v.z; B1[2 * (d - 1) + 1] = (float)v.w;
                }
            }
            float RL[10];
            {
                float rv[12];
                #pragma unroll
                for (int d = 0; d < 3; d++) {
                    float4 v = *(const float4*)(st + OFF_RL + (swz16(2 * tid + d) << 4));
                    rv[4 * d] = v.x; rv[4 * d + 1] = v.y;
                    rv[4 * d + 2] = v.z; rv[4 * d + 3] = v.w;
                }
                #pragma unroll
                for (int j = 1; j <= 9; j++) RL[j] = rv[j + 2];
            }

            // pass A: per-edge angles
            float phi[11];
            #pragma unroll
            for (int m = 0; m < 11; m++) phi[m] = edge_atan2f(Ey[m], Ex[m]);

            // pass B: hinge g, c_m = g_{m-1} - g_m
            float c[10];
            float gprev = 0.f;
            #pragma unroll
            for (int i = 0; i < 10; i++) {
                float theta = phi[i + 1] - phi[i];
                float th = TH[i];
                bool m0 = fmaf(theta, B0[i], th) > 0.f;
                bool m1 = fmaf(theta, B1[i], th) > 0.f;
                float keff = (m0 ? k_stiff : k_soft) + (m1 ? k_stiff : k_soft);
                float diff = theta - th;
                float g = keff * diff;
                if (i >= 2) rot_e = fmaf(g, diff, rot_e);
                if (i >= 1) c[i] = gprev - g;
                gprev = g;
            }

            // pass C: combined per-edge force, scatter
            float Gx[PPT], Gy[PPT];
            #pragma unroll
            for (int j = 0; j < PPT; j++) { Gx[j] = 0.f; Gy[j] = 0.f; }
            #pragma unroll
            for (int m = 1; m <= 9; m++) {
                float ex = Ex[m], ey = Ey[m];
                float lensq = fmaf(ex, ex, ey * ey);
                float rsq = rsqrtf(lensq);
                float len = lensq * rsq;
                float dl  = len - RL[m];
                if (m >= 2) str_e = fmaf(dl, dl, str_e);
                float fsc = k_stretch * dl * rsq;
                float psc = c[m] * rsq * rsq;
                float Fx = fmaf(fsc, ex, -psc * ey);
                float Fy = fmaf(fsc, ey,  psc * ex);
                if (m <= 8) { Gx[m - 1] += Fx; Gy[m - 1] += Fy; }
                if (m >= 2) { Gx[m - 2] -= Fx; Gy[m - 2] -= Fy; }
            }

            // writes (interior => p >= 2 and in-bounds)
            out[3 + 2 * s] = -Gx[0];
            float4* o4 = (float4*)(out + 4 + 2 * s);
            o4[0] = make_float4(-Gy[0], -Gx[1], -Gy[1], -Gx[2]);
            o4[1] = make_float4(-Gy[2], -Gx[3], -Gy[3], -Gx[4]);
            o4[2] = make_float4(-Gy[4], -Gx[5], -Gy[5], -Gx[6]);
            out[16 + 2 * s] = -Gy[6];
            out[17 + 2 * s] = -Gx[7];
            out[18 + 2 * s] = -Gy[7];
        } else {
            compute_direct(pos, th_ss, rest, buckle, out, H, N, s,
                           k_stiff, k_soft, k_stretch, rot_e, str_e);
        }
        __syncthreads();
    }

    // ---------------- energy reduction ----------------
    float r = rot_e, sv = str_e;
    #pragma unroll
    for (int off = 16; off > 0; off >>= 1) {
        r  += __shfl_down_sync(0xffffffffu, r,  off);
        sv += __shfl_down_sync(0xffffffffu, sv, off);
    }
    const int lane = tid & 31;
    const int wid  = tid >> 5;
    if (lane == 0) {
        int slot = (bid * (TPB / 32) + wid) & 63;
        atomicAdd(&g_rot_acc[slot], 0.5 * (double)r);
        atomicAdd(&g_str_acc[slot], 0.5 * (double)k_stretch * (double)sv);
        __threadfence();
        unsigned tk = atomicAdd(&g_ticket, 1u);
        if (tk == totalWarps - 1u) {
            double R = 0.0, S = 0.0;
            #pragma unroll
            for (int i = 0; i < 64; i++) {
                R += g_rot_acc[i]; g_rot_acc[i] = 0.0;
                S += g_str_acc[i]; g_str_acc[i] = 0.0;
            }
            out[0] = (float)(R + S);
            out[1] = (float)R;
            out[2] = (float)S;
            g_ticket = 0u;
        }
    }
}

extern "C" void kernel_launch(void* const* d_in, const int* in_sizes, int n_in,
                              void* d_out, int out_size) {
    const float2* pos      = (const float2*)d_in[0];
    const float*  th_ss    = (const float*)d_in[1];
    const float*  rest     = (const float*)d_in[2];
    const float*  kstiff   = (const float*)d_in[3];
    const float*  ksoft    = (const float*)d_in[4];
    const float*  kstretch = (const float*)d_in[5];
    const int2*   buckle   = (const int2*)d_in[6];
    float* out = (float*)d_out;

    const int H = in_sizes[1];
    const int N = H + 2;
    const int T = (N + TILE - 1) / TILE;
    int blocks = NCTAS < T ? NCTAS : T;
    const unsigned totalWarps = (unsigned)blocks * (TPB / 32);
    const int smem = 2 * STAGE_BYTES;   // 50176

    cudaFuncSetAttribute(chain_kernel,
                         cudaFuncAttributeMaxDynamicSharedMemorySize, smem);
    chain_kernel<<<blocks, TPB, smem>>>(pos, th_ss, rest, kstiff, ksoft,
                                        kstretch, buckle, out, H, totalWarps);
}